// round 4
// baseline (speedup 1.0000x reference)
#include <cuda_runtime.h>
#include <math.h>

// Problem constants
#define BB 2
#define SS 2048
#define DM 2048
#define HH 16
#define DH 128
#define NBH (BB*HH)          // 32 batched (b,h) pairs
#define MROWS (BB*SS)        // 4096

// ---------------- scratch (static device allocations; no cudaMalloc allowed) ----
__device__ float g_q[MROWS * DM];        // 33.5 MB  (B,S,H,DH) flat
__device__ float g_k[MROWS * DM];
__device__ float g_v[MROWS * DM];
__device__ float g_ao[MROWS * DM];       // attention output (B,S,H*DH)
__device__ float g_scores[(size_t)NBH * SS * SS];  // 536 MB

// ---------------- GEMM: C = alpha * A @ op(B) ---------------------------------
// NT=true : B is [N,K] row-major (C[m,n] = sum_k A[m,k]*B[n,k])
// NT=false: B is [K,N] row-major (C[m,n] = sum_k A[m,k]*B[k,n])
// Tiles: BM=BN=128, BK=8; 256 threads, 8x8 per thread.
#define BM 128
#define BN 128
#define BK 8

template <bool NT>
__global__ void __launch_bounds__(256) gemm_kernel(
    const float* __restrict__ A, const float* __restrict__ B, float* __restrict__ C,
    int K, int lda, int ldb, int ldc,
    size_t sA, size_t sB, size_t sC, float alpha)
{
    A += (size_t)blockIdx.z * sA;
    B += (size_t)blockIdx.z * sB;
    C += (size_t)blockIdx.z * sC;

    __shared__ float As[BK][BM];
    __shared__ float Bs[BK][BN];

    const int tid = threadIdx.x;
    const int tx = tid & 15;          // 16 col groups
    const int ty = tid >> 4;          // 16 row groups
    const int row0 = blockIdx.y * BM;
    const int col0 = blockIdx.x * BN;

    // A-tile (and NT B-tile) load mapping: 128 rows x 8 k, one float4 per thread
    const int lr = tid >> 1;           // 0..127
    const int lc = (tid & 1) * 4;      // 0 or 4
    // NN B-tile load mapping: 8 k-rows x 128 n, one float4 per thread
    const int bkr = tid >> 5;          // 0..7
    const int bkc = (tid & 31) * 4;    // 0..124

    float acc[8][8] = {};

    for (int k0 = 0; k0 < K; k0 += BK) {
        float4 a4 = *reinterpret_cast<const float4*>(
            &A[(size_t)(row0 + lr) * lda + k0 + lc]);
        As[lc + 0][lr] = a4.x;
        As[lc + 1][lr] = a4.y;
        As[lc + 2][lr] = a4.z;
        As[lc + 3][lr] = a4.w;

        if (NT) {
            float4 b4 = *reinterpret_cast<const float4*>(
                &B[(size_t)(col0 + lr) * ldb + k0 + lc]);
            Bs[lc + 0][lr] = b4.x;
            Bs[lc + 1][lr] = b4.y;
            Bs[lc + 2][lr] = b4.z;
            Bs[lc + 3][lr] = b4.w;
        } else {
            float4 b4 = *reinterpret_cast<const float4*>(
                &B[(size_t)(k0 + bkr) * ldb + col0 + bkc]);
            *reinterpret_cast<float4*>(&Bs[bkr][bkc]) = b4;
        }
        __syncthreads();

        #pragma unroll
        for (int kk = 0; kk < BK; kk++) {
            float a[8], b[8];
            float4 t0 = *reinterpret_cast<const float4*>(&As[kk][ty * 8]);
            float4 t1 = *reinterpret_cast<const float4*>(&As[kk][ty * 8 + 4]);
            a[0]=t0.x; a[1]=t0.y; a[2]=t0.z; a[3]=t0.w;
            a[4]=t1.x; a[5]=t1.y; a[6]=t1.z; a[7]=t1.w;
            float4 u0 = *reinterpret_cast<const float4*>(&Bs[kk][tx * 8]);
            float4 u1 = *reinterpret_cast<const float4*>(&Bs[kk][tx * 8 + 4]);
            b[0]=u0.x; b[1]=u0.y; b[2]=u0.z; b[3]=u0.w;
            b[4]=u1.x; b[5]=u1.y; b[6]=u1.z; b[7]=u1.w;
            #pragma unroll
            for (int i = 0; i < 8; i++)
                #pragma unroll
                for (int j = 0; j < 8; j++)
                    acc[i][j] = fmaf(a[i], b[j], acc[i][j]);
        }
        __syncthreads();
    }

    #pragma unroll
    for (int i = 0; i < 8; i++) {
        float* cp = &C[(size_t)(row0 + ty * 8 + i) * ldc + col0 + tx * 8];
        #pragma unroll
        for (int j = 0; j < 8; j += 4) {
            float4 o;
            o.x = alpha * acc[i][j + 0];
            o.y = alpha * acc[i][j + 1];
            o.z = alpha * acc[i][j + 2];
            o.w = alpha * acc[i][j + 3];
            *reinterpret_cast<float4*>(&cp[j]) = o;
        }
    }
}

// ---------------- RMSNorm + RoPE (in place on q or k) --------------------------
// One 64-thread block per (b,s,h) head vector of 128.
// rope: out[i]    = F[s,i,0,0]*n[i] + F[s,i,0,1]*n[i+64]
//       out[i+64] = F[s,i,1,0]*n[i] + F[s,i,1,1]*n[i+64]
__global__ void __launch_bounds__(64) rmsnorm_rope_kernel(
    float* __restrict__ t, const float* __restrict__ w, const float* __restrict__ freqs)
{
    const int idx = blockIdx.x;              // b*S*H + s*H + h
    const int s = (idx / HH) % SS;
    float* v = t + (size_t)idx * DH;
    const int i = threadIdx.x;               // 0..63

    float x0 = v[i];
    float x1 = v[i + 64];
    float ss = x0 * x0 + x1 * x1;
    #pragma unroll
    for (int o = 16; o > 0; o >>= 1) ss += __shfl_xor_sync(0xffffffffu, ss, o);
    __shared__ float sm[2];
    if ((i & 31) == 0) sm[i >> 5] = ss;
    __syncthreads();
    float total = sm[0] + sm[1];
    float r = rsqrtf(total * (1.0f / 128.0f) + 1e-6f);

    float n0 = x0 * r * w[i];
    float n1 = x1 * r * w[i + 64];

    const float* F = freqs + (size_t)s * 256 + i * 4;  // (S,1,64,2,2)
    v[i]      = F[0] * n0 + F[1] * n1;
    v[i + 64] = F[2] * n0 + F[3] * n1;
}

// ---------------- Softmax over rows of length 2048 (in place) ------------------
__global__ void __launch_bounds__(256) softmax_kernel(float* __restrict__ data)
{
    float* p = data + (size_t)blockIdx.x * SS;
    const int tid = threadIdx.x;
    __shared__ float sm[8];

    float vals[8];
    float m = -1e30f;
    #pragma unroll
    for (int j = 0; j < 8; j++) {
        vals[j] = p[tid + j * 256];
        m = fmaxf(m, vals[j]);
    }
    #pragma unroll
    for (int o = 16; o > 0; o >>= 1) m = fmaxf(m, __shfl_xor_sync(0xffffffffu, m, o));
    if ((tid & 31) == 0) sm[tid >> 5] = m;
    __syncthreads();
    m = sm[0];
    #pragma unroll
    for (int wgt = 1; wgt < 8; wgt++) m = fmaxf(m, sm[wgt]);
    __syncthreads();

    float sum = 0.0f;
    #pragma unroll
    for (int j = 0; j < 8; j++) {
        vals[j] = __expf(vals[j] - m);
        sum += vals[j];
    }
    #pragma unroll
    for (int o = 16; o > 0; o >>= 1) sum += __shfl_xor_sync(0xffffffffu, sum, o);
    if ((tid & 31) == 0) sm[tid >> 5] = sum;
    __syncthreads();
    float tot = 0.0f;
    #pragma unroll
    for (int wgt = 0; wgt < 8; wgt++) tot += sm[wgt];
    float inv = 1.0f / tot;
    #pragma unroll
    for (int j = 0; j < 8; j++) p[tid + j * 256] = vals[j] * inv;
}

// ---------------- launch -------------------------------------------------------
extern "C" void kernel_launch(void* const* d_in, const int* in_sizes, int n_in,
                              void* d_out, int out_size)
{
    const float* x     = (const float*)d_in[0];  // (B,S,DM)
    const float* rope  = (const float*)d_in[1];  // (S,1,64,2,2)
    const float* wq    = (const float*)d_in[2];  // (DM,DM)
    const float* wk    = (const float*)d_in[3];
    const float* wv    = (const float*)d_in[4];
    const float* wo    = (const float*)d_in[5];
    const float* qnw   = (const float*)d_in[6];  // (DH,)
    const float* knw   = (const float*)d_in[7];
    float* out = (float*)d_out;

    float *q, *k, *v, *ao, *sc;
    cudaGetSymbolAddress((void**)&q,  g_q);
    cudaGetSymbolAddress((void**)&k,  g_k);
    cudaGetSymbolAddress((void**)&v,  g_v);
    cudaGetSymbolAddress((void**)&ao, g_ao);
    cudaGetSymbolAddress((void**)&sc, g_scores);

    const float scale = 0.08838834764831845f;  // 1/sqrt(128)

    // ---- QKV projections: (4096 x 2048) = x @ W^T, NT -------------------------
    {
        dim3 grid(DM / BN, MROWS / BM, 1);
        gemm_kernel<true><<<grid, 256>>>(x, wq, q, DM, DM, DM, DM, 0, 0, 0, 1.0f);
        gemm_kernel<true><<<grid, 256>>>(x, wk, k, DM, DM, DM, DM, 0, 0, 0, 1.0f);
        gemm_kernel<true><<<grid, 256>>>(x, wv, v, DM, DM, DM, DM, 0, 0, 0, 1.0f);
    }

    // ---- RMSNorm + RoPE on q and k -------------------------------------------
    rmsnorm_rope_kernel<<<BB * SS * HH, 64>>>(q, qnw, rope);
    rmsnorm_rope_kernel<<<BB * SS * HH, 64>>>(k, knw, rope);

    // ---- scores[b,h] = scale * q[b,:,h,:] @ k[b,:,h,:]^T  (NT, K=128) --------
    // batch z = b*HH + h; A base offset = b*S*DM + h*DH; use explicit per-z strides
    {
        dim3 grid(SS / BN, SS / BM, NBH);
        // stride trick: base pointer at b=0,h=0; per-z stride for q/k is DH for h
        // but b jumps S*DM. Handle by passing strides that work for z = b*HH+h:
        // launch per-b instead to keep strides linear.
        for (int b = 0; b < BB; b++) {
            dim3 g2(SS / BN, SS / BM, HH);
            gemm_kernel<true><<<g2, 256>>>(
                q + (size_t)b * SS * DM, k + (size_t)b * SS * DM,
                sc + (size_t)b * HH * SS * SS,
                DH, DM, DM, SS,
                (size_t)DH, (size_t)DH, (size_t)SS * SS, scale);
        }
    }

    // ---- softmax over last dim ------------------------------------------------
    softmax_kernel<<<NBH * SS, 256>>>(sc);

    // ---- attn @ V: per (b,h): (2048x2048)@(2048x128), NN ----------------------
    {
        for (int b = 0; b < BB; b++) {
            dim3 g3(DH / BN + ((DH % BN) ? 1 : 0), SS / BM, HH);  // DH=128 -> x=1
            gemm_kernel<false><<<dim3(1, SS / BM, HH), 256>>>(
                sc + (size_t)b * HH * SS * SS, v + (size_t)b * SS * DM,
                ao + (size_t)b * SS * DM,
                SS, SS, DM, DM,
                (size_t)SS * SS, (size_t)DH, (size_t)DH, 1.0f);
        }
    }

    // ---- output projection: out = ao @ wo^T -----------------------------------
    {
        dim3 grid(DM / BN, MROWS / BM, 1);
        gemm_kernel<true><<<grid, 256>>>(ao, wo, out, DM, DM, DM, DM, 0, 0, 0, 1.0f);
    }
}

// round 6
// speedup vs baseline: 2.3370x; 2.3370x over previous
#include <cuda_runtime.h>
#include <cuda_bf16.h>
#include <math.h>
#include <stdint.h>

// Problem constants
#define BB 2
#define SS 2048
#define DM 2048
#define HH 16
#define DH 128
#define NBH (BB*HH)
#define MROWS (BB*SS)        // 4096

// ---------------- scratch ------------------------------------------------------
__device__ float g_q[MROWS * DM];                  // (B,S,H,DH)
__device__ float g_k[MROWS * DM];
__device__ float g_v[(size_t)BB * HH * DH * SS];   // V transposed: (B,H,DH,S)
__device__ float g_ao[MROWS * DM];                 // attention out (B,S,H*DH)
__device__ float g_scores[(size_t)NBH * SS * SS];  // 536 MB

// ---------------- bf16 split helpers -------------------------------------------
__device__ __forceinline__ void split2(float a, float b, uint32_t& hi, uint32_t& lo) {
    __nv_bfloat16 ha = __float2bfloat16_rn(a);
    __nv_bfloat16 hb = __float2bfloat16_rn(b);
    __nv_bfloat16 la = __float2bfloat16_rn(a - __bfloat162float(ha));
    __nv_bfloat16 lb = __float2bfloat16_rn(b - __bfloat162float(hb));
    __nv_bfloat162 h2 = __halves2bfloat162(ha, hb);
    __nv_bfloat162 l2 = __halves2bfloat162(la, lb);
    hi = *reinterpret_cast<uint32_t*>(&h2);
    lo = *reinterpret_cast<uint32_t*>(&l2);
}

__device__ __forceinline__ void mma_bf16(float c[4],
    uint32_t a0, uint32_t a1, uint32_t a2, uint32_t a3,
    uint32_t b0, uint32_t b1)
{
    asm volatile(
        "mma.sync.aligned.m16n8k16.row.col.f32.bf16.bf16.f32 "
        "{%0,%1,%2,%3},{%4,%5,%6,%7},{%8,%9},{%0,%1,%2,%3};"
        : "+f"(c[0]), "+f"(c[1]), "+f"(c[2]), "+f"(c[3])
        : "r"(a0), "r"(a1), "r"(a2), "r"(a3), "r"(b0), "r"(b1));
}

// ---------------- tensor-core GEMM (NT): C = alpha * A @ B^T -------------------
// A: [M,K] row-major, B: [N,K] row-major.
// C[m,n] = sum_k A[m,k]*B[n,k], computed with bf16 hi/lo 3-term split.
// Tiles: 128x128x32; 256 threads = 8 warps (2m x 4n), 64x32 per warp.
// TV=true: C store is the transposed-V epilogue (vt[b,h,d,s]).
#define TBM 128
#define TBN 128
#define TBK 32
#define SAS 40   // bf16 elements per smem row (32 + 8 pad)

template <bool TV>
__global__ void __launch_bounds__(256) mma_gemm(
    const float* __restrict__ A, const float* __restrict__ B, float* __restrict__ C,
    int K, int lda, int ldb, int ldc,
    size_t sA, size_t sB, size_t sC, float alpha)
{
    A += (size_t)blockIdx.z * sA;
    B += (size_t)blockIdx.z * sB;
    C += (size_t)blockIdx.z * sC;

    __shared__ __nv_bfloat16 Ah[TBM * SAS];
    __shared__ __nv_bfloat16 Al[TBM * SAS];
    __shared__ __nv_bfloat16 Bh[TBN * SAS];
    __shared__ __nv_bfloat16 Bl[TBN * SAS];

    const int tid  = threadIdx.x;
    const int lane = tid & 31;
    const int wid  = tid >> 5;
    const int wm   = wid & 1;        // 0..1
    const int wn   = wid >> 1;       // 0..3
    const int row0 = blockIdx.y * TBM;
    const int col0 = blockIdx.x * TBN;

    // gmem->reg staging: 128 rows x 32 k, one float4 per thread per quarter
    const int ar = tid >> 3;          // 0..31
    const int ac = (tid & 7) * 4;     // k offset

    float4 ra[4], rb[4];

    auto load_tile = [&](int k0) {
        #pragma unroll
        for (int r = 0; r < 4; r++) {
            ra[r] = *reinterpret_cast<const float4*>(
                &A[(size_t)(row0 + ar + 32 * r) * lda + k0 + ac]);
            rb[r] = *reinterpret_cast<const float4*>(
                &B[(size_t)(col0 + ar + 32 * r) * ldb + k0 + ac]);
        }
    };

    auto store_tile = [&]() {
        #pragma unroll
        for (int r = 0; r < 4; r++) {
            const int off = (ar + 32 * r) * SAS + ac;
            uint32_t h0, l0, h1, l1;
            split2(ra[r].x, ra[r].y, h0, l0);
            split2(ra[r].z, ra[r].w, h1, l1);
            *reinterpret_cast<uint32_t*>(&Ah[off])     = h0;
            *reinterpret_cast<uint32_t*>(&Ah[off + 2]) = h1;
            *reinterpret_cast<uint32_t*>(&Al[off])     = l0;
            *reinterpret_cast<uint32_t*>(&Al[off + 2]) = l1;
            split2(rb[r].x, rb[r].y, h0, l0);
            split2(rb[r].z, rb[r].w, h1, l1);
            *reinterpret_cast<uint32_t*>(&Bh[off])     = h0;
            *reinterpret_cast<uint32_t*>(&Bh[off + 2]) = h1;
            *reinterpret_cast<uint32_t*>(&Bl[off])     = l0;
            *reinterpret_cast<uint32_t*>(&Bl[off + 2]) = l1;
        }
    };

    float acc[4][4][4] = {};   // [mtile][ntile][frag]

    load_tile(0);
    store_tile();
    __syncthreads();

    for (int k0 = 0; k0 < K; k0 += TBK) {
        const bool more = (k0 + TBK) < K;
        if (more) load_tile(k0 + TBK);

        #pragma unroll
        for (int kk = 0; kk < 2; kk++) {              // two k16 chunks
            const int kb = kk * 16 + (lane & 3) * 2;
            uint32_t ah[4][4], al[4][4];
            #pragma unroll
            for (int i = 0; i < 4; i++) {
                const int m = wm * 64 + i * 16 + (lane >> 2);
                ah[i][0] = *reinterpret_cast<const uint32_t*>(&Ah[m * SAS + kb]);
                ah[i][1] = *reinterpret_cast<const uint32_t*>(&Ah[(m + 8) * SAS + kb]);
                ah[i][2] = *reinterpret_cast<const uint32_t*>(&Ah[m * SAS + kb + 8]);
                ah[i][3] = *reinterpret_cast<const uint32_t*>(&Ah[(m + 8) * SAS + kb + 8]);
                al[i][0] = *reinterpret_cast<const uint32_t*>(&Al[m * SAS + kb]);
                al[i][1] = *reinterpret_cast<const uint32_t*>(&Al[(m + 8) * SAS + kb]);
                al[i][2] = *reinterpret_cast<const uint32_t*>(&Al[m * SAS + kb + 8]);
                al[i][3] = *reinterpret_cast<const uint32_t*>(&Al[(m + 8) * SAS + kb + 8]);
            }
            uint32_t bh[4][2], bl[4][2];
            #pragma unroll
            for (int j = 0; j < 4; j++) {
                const int n = wn * 32 + j * 8 + (lane >> 2);
                bh[j][0] = *reinterpret_cast<const uint32_t*>(&Bh[n * SAS + kb]);
                bh[j][1] = *reinterpret_cast<const uint32_t*>(&Bh[n * SAS + kb + 8]);
                bl[j][0] = *reinterpret_cast<const uint32_t*>(&Bl[n * SAS + kb]);
                bl[j][1] = *reinterpret_cast<const uint32_t*>(&Bl[n * SAS + kb + 8]);
            }
            #pragma unroll
            for (int i = 0; i < 4; i++)
                #pragma unroll
                for (int j = 0; j < 4; j++) {
                    mma_bf16(acc[i][j], ah[i][0], ah[i][1], ah[i][2], ah[i][3],
                             bh[j][0], bh[j][1]);
                    mma_bf16(acc[i][j], ah[i][0], ah[i][1], ah[i][2], ah[i][3],
                             bl[j][0], bl[j][1]);
                    mma_bf16(acc[i][j], al[i][0], al[i][1], al[i][2], al[i][3],
                             bh[j][0], bh[j][1]);
                }
        }
        __syncthreads();
        if (more) {
            store_tile();
            __syncthreads();
        }
    }

    // ---- epilogue -------------------------------------------------------------
    if (TV) {
        // transposed V store: vt[b, h=blockIdx.x, d, s], C = vt base
        const int b = row0 / SS;
        float* vt = C + ((size_t)(b * HH + blockIdx.x) * DH) * SS;
        #pragma unroll
        for (int i = 0; i < 4; i++) {
            const int s = (row0 - b * SS) + wm * 64 + i * 16 + (lane >> 2);
            #pragma unroll
            for (int j = 0; j < 4; j++) {
                const int d = wn * 32 + j * 8 + 2 * (lane & 3);
                vt[(size_t)d * SS + s]           = acc[i][j][0];
                vt[(size_t)(d + 1) * SS + s]     = acc[i][j][1];
                vt[(size_t)d * SS + s + 8]       = acc[i][j][2];
                vt[(size_t)(d + 1) * SS + s + 8] = acc[i][j][3];
            }
        }
    } else {
        #pragma unroll
        for (int i = 0; i < 4; i++) {
            const int r = row0 + wm * 64 + i * 16 + (lane >> 2);
            #pragma unroll
            for (int j = 0; j < 4; j++) {
                const int cc = col0 + wn * 32 + j * 8 + 2 * (lane & 3);
                float2 lo = make_float2(alpha * acc[i][j][0], alpha * acc[i][j][1]);
                float2 hi = make_float2(alpha * acc[i][j][2], alpha * acc[i][j][3]);
                *reinterpret_cast<float2*>(&C[(size_t)r * ldc + cc]) = lo;
                *reinterpret_cast<float2*>(&C[(size_t)(r + 8) * ldc + cc]) = hi;
            }
        }
    }
}

// ---------------- RMSNorm + RoPE (in place on q or k) --------------------------
__global__ void __launch_bounds__(64) rmsnorm_rope_kernel(
    float* __restrict__ t, const float* __restrict__ w, const float* __restrict__ freqs)
{
    const int idx = blockIdx.x;              // b*S*H + s*H + h
    const int s = (idx / HH) % SS;
    float* v = t + (size_t)idx * DH;
    const int i = threadIdx.x;               // 0..63

    float x0 = v[i];
    float x1 = v[i + 64];
    float ss = x0 * x0 + x1 * x1;
    #pragma unroll
    for (int o = 16; o > 0; o >>= 1) ss += __shfl_xor_sync(0xffffffffu, ss, o);
    __shared__ float sm[2];
    if ((i & 31) == 0) sm[i >> 5] = ss;
    __syncthreads();
    float total = sm[0] + sm[1];
    float r = rsqrtf(total * (1.0f / 128.0f) + 1e-6f);

    float n0 = x0 * r * w[i];
    float n1 = x1 * r * w[i + 64];

    const float* F = freqs + (size_t)s * 256 + i * 4;  // (S,1,64,2,2)
    v[i]      = F[0] * n0 + F[1] * n1;
    v[i + 64] = F[2] * n0 + F[3] * n1;
}

// ---------------- Softmax over rows of length 2048 (in place) ------------------
__global__ void __launch_bounds__(256) softmax_kernel(float* __restrict__ data)
{
    float* p = data + (size_t)blockIdx.x * SS;
    const int tid = threadIdx.x;
    __shared__ float sm[8];

    float vals[8];
    float m = -1e30f;
    #pragma unroll
    for (int j = 0; j < 8; j++) {
        vals[j] = p[tid + j * 256];
        m = fmaxf(m, vals[j]);
    }
    #pragma unroll
    for (int o = 16; o > 0; o >>= 1) m = fmaxf(m, __shfl_xor_sync(0xffffffffu, m, o));
    if ((tid & 31) == 0) sm[tid >> 5] = m;
    __syncthreads();
    m = sm[0];
    #pragma unroll
    for (int wgt = 1; wgt < 8; wgt++) m = fmaxf(m, sm[wgt]);
    __syncthreads();

    float sum = 0.0f;
    #pragma unroll
    for (int j = 0; j < 8; j++) {
        vals[j] = __expf(vals[j] - m);
        sum += vals[j];
    }
    #pragma unroll
    for (int o = 16; o > 0; o >>= 1) sum += __shfl_xor_sync(0xffffffffu, sum, o);
    if ((tid & 31) == 0) sm[tid >> 5] = sum;
    __syncthreads();
    float tot = 0.0f;
    #pragma unroll
    for (int wgt = 0; wgt < 8; wgt++) tot += sm[wgt];
    float inv = 1.0f / tot;
    #pragma unroll
    for (int j = 0; j < 8; j++) p[tid + j * 256] = vals[j] * inv;
}

// ---------------- launch -------------------------------------------------------
extern "C" void kernel_launch(void* const* d_in, const int* in_sizes, int n_in,
                              void* d_out, int out_size)
{
    const float* x     = (const float*)d_in[0];  // (B,S,DM)
    const float* rope  = (const float*)d_in[1];  // (S,1,64,2,2)
    const float* wq    = (const float*)d_in[2];  // (DM,DM)
    const float* wk    = (const float*)d_in[3];
    const float* wv    = (const float*)d_in[4];
    const float* wo    = (const float*)d_in[5];
    const float* qnw   = (const float*)d_in[6];
    const float* knw   = (const float*)d_in[7];
    float* out = (float*)d_out;

    float *q, *k, *vt, *ao, *sc;
    cudaGetSymbolAddress((void**)&q,  g_q);
    cudaGetSymbolAddress((void**)&k,  g_k);
    cudaGetSymbolAddress((void**)&vt, g_v);
    cudaGetSymbolAddress((void**)&ao, g_ao);
    cudaGetSymbolAddress((void**)&sc, g_scores);

    const float scale = 0.08838834764831845f;  // 1/sqrt(128)

    // ---- QKV projections: x @ W^T (NT). V goes out transposed per head. ------
    {
        dim3 grid(DM / TBN, MROWS / TBM, 1);
        mma_gemm<false><<<grid, 256>>>(x, wq, q,  DM, DM, DM, DM, 0, 0, 0, 1.0f);
        mma_gemm<false><<<grid, 256>>>(x, wk, k,  DM, DM, DM, DM, 0, 0, 0, 1.0f);
        mma_gemm<true ><<<grid, 256>>>(x, wv, vt, DM, DM, DM, 0,  0, 0, 0, 1.0f);
    }

    // ---- RMSNorm + RoPE on q and k -------------------------------------------
    rmsnorm_rope_kernel<<<BB * SS * HH, 64>>>(q, qnw, rope);
    rmsnorm_rope_kernel<<<BB * SS * HH, 64>>>(k, knw, rope);

    // ---- scores[b,h] = scale * q @ k^T (NT, K=128) ---------------------------
    for (int b = 0; b < BB; b++) {
        dim3 g2(SS / TBN, SS / TBM, HH);
        mma_gemm<false><<<g2, 256>>>(
            q + (size_t)b * SS * DM, k + (size_t)b * SS * DM,
            sc + (size_t)b * HH * SS * SS,
            DH, DM, DM, SS,
            (size_t)DH, (size_t)DH, (size_t)SS * SS, scale);
    }

    // ---- softmax over last dim ------------------------------------------------
    softmax_kernel<<<NBH * SS, 256>>>(sc);

    // ---- attn @ V via NT on transposed V: C[s,d] = sum_k P[s,k]*vt[d,k] -------
    for (int b = 0; b < BB; b++) {
        mma_gemm<false><<<dim3(1, SS / TBM, HH), 256>>>(
            sc + (size_t)b * HH * SS * SS,
            vt + (size_t)b * HH * DH * SS,
            ao + (size_t)b * SS * DM,
            SS, SS, SS, DM,
            (size_t)SS * SS, (size_t)DH * SS, (size_t)DH, 1.0f);
    }

    // ---- output projection: out = ao @ wo^T -----------------------------------
    {
        dim3 grid(DM / TBN, MROWS / TBM, 1);
        mma_gemm<false><<<grid, 256>>>(ao, wo, out, DM, DM, DM, DM, 0, 0, 0, 1.0f);
    }
}

// round 7
// speedup vs baseline: 2.6759x; 1.1450x over previous
#include <cuda_runtime.h>
#include <cuda_bf16.h>
#include <math.h>
#include <stdint.h>

// Problem constants
#define BB 2
#define SS 2048
#define DM 2048
#define HH 16
#define DH 128
#define NBH (BB*HH)
#define MROWS (BB*SS)        // 4096

// ---------------- scratch ------------------------------------------------------
__device__ float g_q[MROWS * DM];                  // (B,S,H,DH)
__device__ float g_k[MROWS * DM];
__device__ float g_v[(size_t)BB * HH * DH * SS];   // V transposed: (B,H,DH,S)
__device__ float g_ao[MROWS * DM];                 // attention out (B,S,H*DH)

// ---------------- bf16 split helpers -------------------------------------------
__device__ __forceinline__ void split2(float a, float b, uint32_t& hi, uint32_t& lo) {
    __nv_bfloat16 ha = __float2bfloat16_rn(a);
    __nv_bfloat16 hb = __float2bfloat16_rn(b);
    __nv_bfloat16 la = __float2bfloat16_rn(a - __bfloat162float(ha));
    __nv_bfloat16 lb = __float2bfloat16_rn(b - __bfloat162float(hb));
    __nv_bfloat162 h2 = __halves2bfloat162(ha, hb);
    __nv_bfloat162 l2 = __halves2bfloat162(la, lb);
    hi = *reinterpret_cast<uint32_t*>(&h2);
    lo = *reinterpret_cast<uint32_t*>(&l2);
}

__device__ __forceinline__ void mma_bf16(float c[4],
    uint32_t a0, uint32_t a1, uint32_t a2, uint32_t a3,
    uint32_t b0, uint32_t b1)
{
    asm volatile(
        "mma.sync.aligned.m16n8k16.row.col.f32.bf16.bf16.f32 "
        "{%0,%1,%2,%3},{%4,%5,%6,%7},{%8,%9},{%0,%1,%2,%3};"
        : "+f"(c[0]), "+f"(c[1]), "+f"(c[2]), "+f"(c[3])
        : "r"(a0), "r"(a1), "r"(a2), "r"(a3), "r"(b0), "r"(b1));
}

// ---------------- tensor-core GEMM (NT): C = alpha * A @ B^T -------------------
// A: [M,K] row-major, B: [N,K] row-major. bf16 hi/lo 3-term split.
// Tiles: 128x128x32; 256 threads = 8 warps (2m x 4n), 64x32 per warp.
// TV=true: C store is the transposed-V epilogue (vt[b,h,d,s]).
#define TBM 128
#define TBN 128
#define TBK 32
#define SAS 40

template <bool TV>
__global__ void __launch_bounds__(256) mma_gemm(
    const float* __restrict__ A, const float* __restrict__ B, float* __restrict__ C,
    int K, int lda, int ldb, int ldc,
    size_t sA, size_t sB, size_t sC, float alpha)
{
    A += (size_t)blockIdx.z * sA;
    B += (size_t)blockIdx.z * sB;
    C += (size_t)blockIdx.z * sC;

    __shared__ __nv_bfloat16 Ah[TBM * SAS];
    __shared__ __nv_bfloat16 Al[TBM * SAS];
    __shared__ __nv_bfloat16 Bh[TBN * SAS];
    __shared__ __nv_bfloat16 Bl[TBN * SAS];

    const int tid  = threadIdx.x;
    const int lane = tid & 31;
    const int wid  = tid >> 5;
    const int wm   = wid & 1;
    const int wn   = wid >> 1;
    const int row0 = blockIdx.y * TBM;
    const int col0 = blockIdx.x * TBN;

    const int ar = tid >> 3;
    const int ac = (tid & 7) * 4;

    float4 ra[4], rb[4];

    auto load_tile = [&](int k0) {
        #pragma unroll
        for (int r = 0; r < 4; r++) {
            ra[r] = *reinterpret_cast<const float4*>(
                &A[(size_t)(row0 + ar + 32 * r) * lda + k0 + ac]);
            rb[r] = *reinterpret_cast<const float4*>(
                &B[(size_t)(col0 + ar + 32 * r) * ldb + k0 + ac]);
        }
    };

    auto store_tile = [&]() {
        #pragma unroll
        for (int r = 0; r < 4; r++) {
            const int off = (ar + 32 * r) * SAS + ac;
            uint32_t h0, l0, h1, l1;
            split2(ra[r].x, ra[r].y, h0, l0);
            split2(ra[r].z, ra[r].w, h1, l1);
            *reinterpret_cast<uint32_t*>(&Ah[off])     = h0;
            *reinterpret_cast<uint32_t*>(&Ah[off + 2]) = h1;
            *reinterpret_cast<uint32_t*>(&Al[off])     = l0;
            *reinterpret_cast<uint32_t*>(&Al[off + 2]) = l1;
            split2(rb[r].x, rb[r].y, h0, l0);
            split2(rb[r].z, rb[r].w, h1, l1);
            *reinterpret_cast<uint32_t*>(&Bh[off])     = h0;
            *reinterpret_cast<uint32_t*>(&Bh[off + 2]) = h1;
            *reinterpret_cast<uint32_t*>(&Bl[off])     = l0;
            *reinterpret_cast<uint32_t*>(&Bl[off + 2]) = l1;
        }
    };

    float acc[4][4][4] = {};

    load_tile(0);
    store_tile();
    __syncthreads();

    for (int k0 = 0; k0 < K; k0 += TBK) {
        const bool more = (k0 + TBK) < K;
        if (more) load_tile(k0 + TBK);

        #pragma unroll
        for (int kk = 0; kk < 2; kk++) {
            const int kb = kk * 16 + (lane & 3) * 2;
            uint32_t ah[4][4], al[4][4];
            #pragma unroll
            for (int i = 0; i < 4; i++) {
                const int m = wm * 64 + i * 16 + (lane >> 2);
                ah[i][0] = *reinterpret_cast<const uint32_t*>(&Ah[m * SAS + kb]);
                ah[i][1] = *reinterpret_cast<const uint32_t*>(&Ah[(m + 8) * SAS + kb]);
                ah[i][2] = *reinterpret_cast<const uint32_t*>(&Ah[m * SAS + kb + 8]);
                ah[i][3] = *reinterpret_cast<const uint32_t*>(&Ah[(m + 8) * SAS + kb + 8]);
                al[i][0] = *reinterpret_cast<const uint32_t*>(&Al[m * SAS + kb]);
                al[i][1] = *reinterpret_cast<const uint32_t*>(&Al[(m + 8) * SAS + kb]);
                al[i][2] = *reinterpret_cast<const uint32_t*>(&Al[m * SAS + kb + 8]);
                al[i][3] = *reinterpret_cast<const uint32_t*>(&Al[(m + 8) * SAS + kb + 8]);
            }
            uint32_t bh[4][2], bl[4][2];
            #pragma unroll
            for (int j = 0; j < 4; j++) {
                const int n = wn * 32 + j * 8 + (lane >> 2);
                bh[j][0] = *reinterpret_cast<const uint32_t*>(&Bh[n * SAS + kb]);
                bh[j][1] = *reinterpret_cast<const uint32_t*>(&Bh[n * SAS + kb + 8]);
                bl[j][0] = *reinterpret_cast<const uint32_t*>(&Bl[n * SAS + kb]);
                bl[j][1] = *reinterpret_cast<const uint32_t*>(&Bl[n * SAS + kb + 8]);
            }
            #pragma unroll
            for (int i = 0; i < 4; i++)
                #pragma unroll
                for (int j = 0; j < 4; j++) {
                    mma_bf16(acc[i][j], ah[i][0], ah[i][1], ah[i][2], ah[i][3],
                             bh[j][0], bh[j][1]);
                    mma_bf16(acc[i][j], ah[i][0], ah[i][1], ah[i][2], ah[i][3],
                             bl[j][0], bl[j][1]);
                    mma_bf16(acc[i][j], al[i][0], al[i][1], al[i][2], al[i][3],
                             bh[j][0], bh[j][1]);
                }
        }
        __syncthreads();
        if (more) {
            store_tile();
            __syncthreads();
        }
    }

    if (TV) {
        const int b = row0 / SS;
        float* vt = C + ((size_t)(b * HH + blockIdx.x) * DH) * SS;
        #pragma unroll
        for (int i = 0; i < 4; i++) {
            const int s = (row0 - b * SS) + wm * 64 + i * 16 + (lane >> 2);
            #pragma unroll
            for (int j = 0; j < 4; j++) {
                const int d = wn * 32 + j * 8 + 2 * (lane & 3);
                vt[(size_t)d * SS + s]           = acc[i][j][0];
                vt[(size_t)(d + 1) * SS + s]     = acc[i][j][1];
                vt[(size_t)d * SS + s + 8]       = acc[i][j][2];
                vt[(size_t)(d + 1) * SS + s + 8] = acc[i][j][3];
            }
        }
    } else {
        #pragma unroll
        for (int i = 0; i < 4; i++) {
            const int r = row0 + wm * 64 + i * 16 + (lane >> 2);
            #pragma unroll
            for (int j = 0; j < 4; j++) {
                const int cc = col0 + wn * 32 + j * 8 + 2 * (lane & 3);
                float2 lo = make_float2(alpha * acc[i][j][0], alpha * acc[i][j][1]);
                float2 hi = make_float2(alpha * acc[i][j][2], alpha * acc[i][j][3]);
                *reinterpret_cast<float2*>(&C[(size_t)r * ldc + cc]) = lo;
                *reinterpret_cast<float2*>(&C[(size_t)(r + 8) * ldc + cc]) = hi;
            }
        }
    }
}

// ---------------- RMSNorm + RoPE (in place on q or k) --------------------------
__global__ void __launch_bounds__(64) rmsnorm_rope_kernel(
    float* __restrict__ t, const float* __restrict__ w, const float* __restrict__ freqs)
{
    const int idx = blockIdx.x;
    const int s = (idx / HH) % SS;
    float* v = t + (size_t)idx * DH;
    const int i = threadIdx.x;

    float x0 = v[i];
    float x1 = v[i + 64];
    float ss = x0 * x0 + x1 * x1;
    #pragma unroll
    for (int o = 16; o > 0; o >>= 1) ss += __shfl_xor_sync(0xffffffffu, ss, o);
    __shared__ float sm[2];
    if ((i & 31) == 0) sm[i >> 5] = ss;
    __syncthreads();
    float total = sm[0] + sm[1];
    float r = rsqrtf(total * (1.0f / 128.0f) + 1e-6f);

    float n0 = x0 * r * w[i];
    float n1 = x1 * r * w[i + 64];

    const float* F = freqs + (size_t)s * 256 + i * 4;
    v[i]      = F[0] * n0 + F[1] * n1;
    v[i + 64] = F[2] * n0 + F[3] * n1;
}

// ---------------- Flash attention ----------------------------------------------
// grid (SS/128 q-tiles, NBH). 256 threads = 8 warps; warp w owns q rows w*16..+15.
// Q fragments live in registers (pre-scaled, hi/lo bf16). K/V tiles (64 kv) in smem.
// S accumulators are reused as P (A-fragment layout == C-fragment layout).
#define FKV 64
#define KST 136   // K smem row stride (bf16): 128 + 8 pad
#define VST 72    // V smem row stride (bf16): 64 + 8 pad

__global__ void __launch_bounds__(256) flash_kernel(
    const float* __restrict__ q, const float* __restrict__ k,
    const float* __restrict__ vt, float* __restrict__ ao)
{
    extern __shared__ __nv_bfloat16 fsm[];
    __nv_bfloat16* Kh = fsm;                    // 64*KST
    __nv_bfloat16* Kl = Kh + FKV * KST;
    __nv_bfloat16* Vh = Kl + FKV * KST;         // 128*VST
    __nv_bfloat16* Vl = Vh + DH * VST;

    const int tid  = threadIdx.x;
    const int lane = tid & 31;
    const int w    = tid >> 5;
    const int g    = lane >> 2;
    const int t    = lane & 3;
    const int bh   = blockIdx.y;
    const int b    = bh >> 4;
    const int h    = bh & 15;
    const int q0   = blockIdx.x * 128;

    const float* qb  = q  + ((size_t)(b * SS + q0)) * DM + h * DH;
    const float* kb  = k  + (size_t)b * SS * DM + h * DH;
    const float* vb  = vt + (size_t)bh * DH * SS;
    float*       aob = ao + ((size_t)(b * SS + q0)) * DM + h * DH;

    const float scale = 0.08838834764831845f;   // 1/sqrt(128)

    // ---- Q fragments in registers (pre-scaled) --------------------------------
    uint32_t qh[8][4], ql[8][4];
    {
        const float* qw = qb + (size_t)(w * 16) * DM;
        #pragma unroll
        for (int kc = 0; kc < 8; kc++) {
            #pragma unroll
            for (int e = 0; e < 4; e++) {
                const int r = g + ((e & 1) ? 8 : 0);
                const int c = kc * 16 + 2 * t + ((e & 2) ? 8 : 0);
                float2 v2 = *reinterpret_cast<const float2*>(&qw[(size_t)r * DM + c]);
                split2(v2.x * scale, v2.y * scale, qh[kc][e], ql[kc][e]);
            }
        }
    }

    float oacc[16][4] = {};
    float m0 = -INFINITY, m1 = -INFINITY, l0 = 0.0f, l1 = 0.0f;

    for (int kv0 = 0; kv0 < SS; kv0 += FKV) {
        __syncthreads();
        // ---- load K tile: 64 kv rows x 128 dh ---------------------------------
        {
            const int row = tid >> 3;            // 0..31 (+32)
            const int cb  = (tid & 7) * 4;       // +32*pc
            #pragma unroll
            for (int pr = 0; pr < 2; pr++) {
                const float* src = kb + (size_t)(kv0 + row + 32 * pr) * DM;
                #pragma unroll
                for (int pc = 0; pc < 4; pc++) {
                    const int c = cb + 32 * pc;
                    float4 v4 = *reinterpret_cast<const float4*>(&src[c]);
                    uint32_t h0, lo0, h1, lo1;
                    split2(v4.x, v4.y, h0, lo0);
                    split2(v4.z, v4.w, h1, lo1);
                    const int off = (row + 32 * pr) * KST + c;
                    *reinterpret_cast<uint32_t*>(&Kh[off])     = h0;
                    *reinterpret_cast<uint32_t*>(&Kh[off + 2]) = h1;
                    *reinterpret_cast<uint32_t*>(&Kl[off])     = lo0;
                    *reinterpret_cast<uint32_t*>(&Kl[off + 2]) = lo1;
                }
            }
        }
        // ---- load V tile: 128 dh rows x 64 kv (from vt) -----------------------
        {
            const int row = tid >> 3;            // 0..31 (+32*pr)
            const int cb  = (tid & 7) * 4;       // +32*pc
            #pragma unroll
            for (int pr = 0; pr < 4; pr++) {
                const float* src = vb + (size_t)(row + 32 * pr) * SS + kv0;
                #pragma unroll
                for (int pc = 0; pc < 2; pc++) {
                    const int c = cb + 32 * pc;
                    float4 v4 = *reinterpret_cast<const float4*>(&src[c]);
                    uint32_t h0, lo0, h1, lo1;
                    split2(v4.x, v4.y, h0, lo0);
                    split2(v4.z, v4.w, h1, lo1);
                    const int off = (row + 32 * pr) * VST + c;
                    *reinterpret_cast<uint32_t*>(&Vh[off])     = h0;
                    *reinterpret_cast<uint32_t*>(&Vh[off + 2]) = h1;
                    *reinterpret_cast<uint32_t*>(&Vl[off])     = lo0;
                    *reinterpret_cast<uint32_t*>(&Vl[off + 2]) = lo1;
                }
            }
        }
        __syncthreads();

        // ---- S = Q @ K^T (16 q x 64 kv per warp) ------------------------------
        float sacc[8][4] = {};
        #pragma unroll
        for (int j = 0; j < 8; j++) {
            #pragma unroll
            for (int kc = 0; kc < 8; kc++) {
                const int off = (j * 8 + g) * KST + kc * 16 + 2 * t;
                uint32_t bh0 = *reinterpret_cast<const uint32_t*>(&Kh[off]);
                uint32_t bh1 = *reinterpret_cast<const uint32_t*>(&Kh[off + 8]);
                uint32_t bl0 = *reinterpret_cast<const uint32_t*>(&Kl[off]);
                uint32_t bl1 = *reinterpret_cast<const uint32_t*>(&Kl[off + 8]);
                mma_bf16(sacc[j], qh[kc][0], qh[kc][1], qh[kc][2], qh[kc][3], bh0, bh1);
                mma_bf16(sacc[j], qh[kc][0], qh[kc][1], qh[kc][2], qh[kc][3], bl0, bl1);
                mma_bf16(sacc[j], ql[kc][0], ql[kc][1], ql[kc][2], ql[kc][3], bh0, bh1);
            }
        }

        // ---- online softmax ---------------------------------------------------
        float mx0 = -INFINITY, mx1 = -INFINITY;
        #pragma unroll
        for (int j = 0; j < 8; j++) {
            mx0 = fmaxf(mx0, fmaxf(sacc[j][0], sacc[j][1]));
            mx1 = fmaxf(mx1, fmaxf(sacc[j][2], sacc[j][3]));
        }
        mx0 = fmaxf(mx0, __shfl_xor_sync(0xffffffffu, mx0, 1));
        mx0 = fmaxf(mx0, __shfl_xor_sync(0xffffffffu, mx0, 2));
        mx1 = fmaxf(mx1, __shfl_xor_sync(0xffffffffu, mx1, 1));
        mx1 = fmaxf(mx1, __shfl_xor_sync(0xffffffffu, mx1, 2));

        const float nm0 = fmaxf(m0, mx0), nm1 = fmaxf(m1, mx1);
        const float al0 = __expf(m0 - nm0), al1 = __expf(m1 - nm1);
        m0 = nm0; m1 = nm1;

        float s0 = 0.0f, s1 = 0.0f;
        #pragma unroll
        for (int j = 0; j < 8; j++) {
            sacc[j][0] = __expf(sacc[j][0] - nm0);
            sacc[j][1] = __expf(sacc[j][1] - nm0);
            sacc[j][2] = __expf(sacc[j][2] - nm1);
            sacc[j][3] = __expf(sacc[j][3] - nm1);
            s0 += sacc[j][0] + sacc[j][1];
            s1 += sacc[j][2] + sacc[j][3];
        }
        s0 += __shfl_xor_sync(0xffffffffu, s0, 1);
        s0 += __shfl_xor_sync(0xffffffffu, s0, 2);
        s1 += __shfl_xor_sync(0xffffffffu, s1, 1);
        s1 += __shfl_xor_sync(0xffffffffu, s1, 2);
        l0 = l0 * al0 + s0;
        l1 = l1 * al1 + s1;

        #pragma unroll
        for (int jn = 0; jn < 16; jn++) {
            oacc[jn][0] *= al0; oacc[jn][1] *= al0;
            oacc[jn][2] *= al1; oacc[jn][3] *= al1;
        }

        // ---- O += P @ V -------------------------------------------------------
        #pragma unroll
        for (int kc2 = 0; kc2 < 4; kc2++) {
            const int j0 = 2 * kc2, j1 = 2 * kc2 + 1;
            uint32_t pa0h, pa0l, pa1h, pa1l, pa2h, pa2l, pa3h, pa3l;
            split2(sacc[j0][0], sacc[j0][1], pa0h, pa0l);
            split2(sacc[j0][2], sacc[j0][3], pa1h, pa1l);
            split2(sacc[j1][0], sacc[j1][1], pa2h, pa2l);
            split2(sacc[j1][2], sacc[j1][3], pa3h, pa3l);
            #pragma unroll
            for (int jn = 0; jn < 16; jn++) {
                const int off = (jn * 8 + g) * VST + kc2 * 16 + 2 * t;
                uint32_t bh0 = *reinterpret_cast<const uint32_t*>(&Vh[off]);
                uint32_t bh1 = *reinterpret_cast<const uint32_t*>(&Vh[off + 8]);
                uint32_t bl0 = *reinterpret_cast<const uint32_t*>(&Vl[off]);
                uint32_t bl1 = *reinterpret_cast<const uint32_t*>(&Vl[off + 8]);
                mma_bf16(oacc[jn], pa0h, pa1h, pa2h, pa3h, bh0, bh1);
                mma_bf16(oacc[jn], pa0h, pa1h, pa2h, pa3h, bl0, bl1);
                mma_bf16(oacc[jn], pa0l, pa1l, pa2l, pa3l, bh0, bh1);
            }
        }
    }

    // ---- epilogue: O /= l, write ----------------------------------------------
    const float inv0 = 1.0f / l0, inv1 = 1.0f / l1;
    #pragma unroll
    for (int jn = 0; jn < 16; jn++) {
        const int r = w * 16 + g;
        const int c = jn * 8 + 2 * t;
        float2 lo = make_float2(oacc[jn][0] * inv0, oacc[jn][1] * inv0);
        float2 hi = make_float2(oacc[jn][2] * inv1, oacc[jn][3] * inv1);
        *reinterpret_cast<float2*>(&aob[(size_t)r * DM + c])       = lo;
        *reinterpret_cast<float2*>(&aob[(size_t)(r + 8) * DM + c]) = hi;
    }
}

// ---------------- launch -------------------------------------------------------
extern "C" void kernel_launch(void* const* d_in, const int* in_sizes, int n_in,
                              void* d_out, int out_size)
{
    const float* x     = (const float*)d_in[0];
    const float* rope  = (const float*)d_in[1];
    const float* wq    = (const float*)d_in[2];
    const float* wk    = (const float*)d_in[3];
    const float* wv    = (const float*)d_in[4];
    const float* wo    = (const float*)d_in[5];
    const float* qnw   = (const float*)d_in[6];
    const float* knw   = (const float*)d_in[7];
    float* out = (float*)d_out;

    float *q, *k, *vt, *ao;
    cudaGetSymbolAddress((void**)&q,  g_q);
    cudaGetSymbolAddress((void**)&k,  g_k);
    cudaGetSymbolAddress((void**)&vt, g_v);
    cudaGetSymbolAddress((void**)&ao, g_ao);

    const int fsmem = (FKV * KST + DH * VST) * 2 * 2 * (int)sizeof(__nv_bfloat16) / 2;
    // = (64*136 + 128*72) * 2 arrays(hi/lo) * 2 bytes
    static_assert((FKV * KST + DH * VST) * 4 == 71680, "smem size");
    cudaFuncSetAttribute(flash_kernel, cudaFuncAttributeMaxDynamicSharedMemorySize, 71680);
    (void)fsmem;

    // ---- QKV projections: x @ W^T (NT). V goes out transposed per head. ------
    {
        dim3 grid(DM / TBN, MROWS / TBM, 1);
        mma_gemm<false><<<grid, 256>>>(x, wq, q,  DM, DM, DM, DM, 0, 0, 0, 1.0f);
        mma_gemm<false><<<grid, 256>>>(x, wk, k,  DM, DM, DM, DM, 0, 0, 0, 1.0f);
        mma_gemm<true ><<<grid, 256>>>(x, wv, vt, DM, DM, DM, 0,  0, 0, 0, 1.0f);
    }

    // ---- RMSNorm + RoPE on q and k -------------------------------------------
    rmsnorm_rope_kernel<<<BB * SS * HH, 64>>>(q, qnw, rope);
    rmsnorm_rope_kernel<<<BB * SS * HH, 64>>>(k, knw, rope);

    // ---- fused attention ------------------------------------------------------
    flash_kernel<<<dim3(SS / 128, NBH), 256, 71680>>>(q, k, vt, ao);

    // ---- output projection: out = ao @ wo^T -----------------------------------
    {
        dim3 grid(DM / TBN, MROWS / TBM, 1);
        mma_gemm<false><<<grid, 256>>>(ao, wo, out, DM, DM, DM, DM, 0, 0, 0, 1.0f);
    }
}